// round 9
// baseline (speedup 1.0000x reference)
#include <cuda_runtime.h>
#include <cuda_bf16.h>
#include <math.h>
#include <stdint.h>

#define HID   1024
#define EMB   512
#define TLEN  2048
#define G4    4096
#define NCTA  128
#define OSIZE 32000
#define K3E   (3*EMB)
#define K3H   (3*HID)

typedef unsigned long long ull;

// ---------------- scratch ----------------
__device__ float g_xg_enc[(size_t)TLEN * G4];
__device__ float g_xg_dec[(size_t)TLEN * G4];
__device__ float g_hs[(size_t)TLEN * HID];
__device__ float g_hbuf[2][HID];
__device__ float g_cenc[HID];
__device__ float g_czero[HID];
__device__ int   g_decidx[TLEN];
__device__ unsigned g_ctr8[8 * 32];   // 8 counters, 128B apart
__device__ __nv_bfloat16 g_A3e[(size_t)TLEN * K3E];
__device__ __nv_bfloat16 g_A3d[(size_t)TLEN * K3E];
__device__ __nv_bfloat16 g_W3e[(size_t)G4 * K3E];
__device__ __nv_bfloat16 g_W3d[(size_t)G4 * K3E];
__device__ __nv_bfloat16 g_B3o[(size_t)OSIZE * K3H];
__device__ __nv_bfloat16 g_A3h[(size_t)TLEN * K3H];

// ---------------- helpers ----------------
__device__ __forceinline__ uint32_t s2u(const void* p) {
    return (uint32_t)__cvta_generic_to_shared(p);
}
__device__ __forceinline__ void cp16(uint32_t dst, const void* src) {
    asm volatile("cp.async.cg.shared.global [%0], [%1], 16;" :: "r"(dst), "l"(src) : "memory");
}
#define CP_COMMIT() asm volatile("cp.async.commit_group;" ::: "memory")
#define CP_WAIT2()  asm volatile("cp.async.wait_group 2;" ::: "memory")

#define LDSM_X4(r0, r1, r2, r3, addr) \
    asm volatile("ldmatrix.sync.aligned.m8n8.x4.shared.b16 {%0,%1,%2,%3}, [%4];" \
                 : "=r"(r0), "=r"(r1), "=r"(r2), "=r"(r3) : "r"(addr))

#define MMA16816(d, a, b0, b1) \
    asm volatile("mma.sync.aligned.m16n8k16.row.col.f32.bf16.bf16.f32 " \
                 "{%0,%1,%2,%3}, {%4,%5,%6,%7}, {%8,%9}, {%0,%1,%2,%3};" \
                 : "+f"((d)[0]), "+f"((d)[1]), "+f"((d)[2]), "+f"((d)[3]) \
                 : "r"((a)[0]), "r"((a)[1]), "r"((a)[2]), "r"((a)[3]), \
                   "r"(b0), "r"(b1))

#define FMA2(acc, w, h) \
    asm("fma.rn.f32x2 %0, %1, %2, %0;" : "+l"(acc) : "l"(w), "l"(h))
#define ADD2(d, a, b) \
    asm("add.rn.f32x2 %0, %1, %2;" : "=l"(d) : "l"(a), "l"(b))

__device__ __forceinline__ float tanh_apx(float x) {
    float r;
    asm("tanh.approx.f32 %0, %1;" : "=f"(r) : "f"(x));
    return r;
}
__device__ __forceinline__ float sigf(float x) {
    return fmaf(tanh_apx(0.5f * x), 0.5f, 0.5f);
}

static __device__ __forceinline__ uint32_t sw128(uint32_t off) {
    return off ^ ((off >> 3) & 0x70);
}

// ---------------- init kernels ----------------
__global__ void init0_kernel(const int* __restrict__ gt) {
    int i = blockIdx.x * blockDim.x + threadIdx.x;
    if (i < 8 * 32) g_ctr8[i] = 0u;
    if (i < HID) { g_hbuf[0][i] = 0.f; g_hbuf[1][i] = 0.f; g_czero[i] = 0.f; }
    if (i < TLEN) g_decidx[i] = (i == 0) ? 1 : gt[i - 1];
}
__global__ void init1_kernel() {
    int i = blockIdx.x * blockDim.x + threadIdx.x;
    if (i < 8 * 32) g_ctr8[i] = 0u;
    if (i < HID) g_hbuf[0][i] = g_cenc[i];
}

// ---------------- bf16 hi/lo split: mode 0 => [hi|lo|hi], mode 1 => [hi|hi|lo] ----------------
__global__ __launch_bounds__(256)
void conv_split(const float* __restrict__ src, const int* __restrict__ idx,
                __nv_bfloat16* __restrict__ dst, int K, long total, int mode)
{
    long i = ((long)blockIdx.x * blockDim.x + threadIdx.x) * 4;
    if (i >= total) return;
    int r = (int)(i / K);
    int k = (int)(i % K);
    int srow = idx ? idx[r] : r;
    float4 v = *(const float4*)(src + (size_t)srow * K + k);

    __nv_bfloat16 hx = __float2bfloat16_rn(v.x), hy = __float2bfloat16_rn(v.y);
    __nv_bfloat16 hz = __float2bfloat16_rn(v.z), hw = __float2bfloat16_rn(v.w);
    __nv_bfloat16 lx = __float2bfloat16_rn(v.x - __bfloat162float(hx));
    __nv_bfloat16 ly = __float2bfloat16_rn(v.y - __bfloat162float(hy));
    __nv_bfloat16 lz = __float2bfloat16_rn(v.z - __bfloat162float(hz));
    __nv_bfloat16 lw = __float2bfloat16_rn(v.w - __bfloat162float(hw));

    size_t base = (size_t)r * 3 * K;
    __nv_bfloat162 h01 = {hx, hy}, h23 = {hz, hw};
    __nv_bfloat162 l01 = {lx, ly}, l23 = {lz, lw};

    *(__nv_bfloat162*)(dst + base + k)     = h01;
    *(__nv_bfloat162*)(dst + base + k + 2) = h23;
    if (mode == 0) {
        *(__nv_bfloat162*)(dst + base + K + k)       = l01;
        *(__nv_bfloat162*)(dst + base + K + k + 2)   = l23;
        *(__nv_bfloat162*)(dst + base + 2*K + k)     = h01;
        *(__nv_bfloat162*)(dst + base + 2*K + k + 2) = h23;
    } else {
        *(__nv_bfloat162*)(dst + base + K + k)       = h01;
        *(__nv_bfloat162*)(dst + base + K + k + 2)   = h23;
        *(__nv_bfloat162*)(dst + base + 2*K + k)     = l01;
        *(__nv_bfloat162*)(dst + base + 2*K + k + 2) = l23;
    }
}

// ---------------- mma.sync bf16 GEMM (unchanged from R8) ----------------
#define ASTG 16384
#define BSTG 32768
#define STG  (ASTG + BSTG)
#define GEMM_SMEM (4 * STG + 2048)

__global__ __launch_bounds__(256, 1)
void gemm_mma3(const __nv_bfloat16* __restrict__ Ag, const __nv_bfloat16* __restrict__ Bg,
               const float* __restrict__ b1, const float* __restrict__ b2,
               float* __restrict__ C, int Mt, int K3, int Ncols, int GN)
{
    extern __shared__ char smem_raw[];
    const uint32_t sraw = s2u(smem_raw);
    const uint32_t sb0  = (sraw + 1023u) & ~1023u;
    float* sbias = (float*)(smem_raw + (sb0 - sraw) + 4 * STG);

    const int tid  = threadIdx.x;
    const int wid  = tid >> 5;
    const int lane = tid & 31;
    const int NC   = K3 >> 6;

    int gw  = Mt * GN;
    int gid = blockIdx.x / gw;
    int rem = blockIdx.x % gw;
    int m0 = (rem % Mt) * 128;
    int n0 = (gid * GN + rem / Mt) * 256;

    sbias[tid] = b1[n0 + tid] + (b2 ? b2[n0 + tid] : 0.f);

    const int rbase = tid >> 3;
    const int seg   = tid & 7;
    uint32_t swA[4], swB[8];
#pragma unroll
    for (int r = 0; r < 4; r++)
        swA[r] = sw128((uint32_t)(rbase + r * 32) * 128u + (uint32_t)seg * 16u);
#pragma unroll
    for (int r = 0; r < 8; r++)
        swB[r] = sw128((uint32_t)(rbase + r * 32) * 128u + (uint32_t)seg * 16u);
    const __nv_bfloat16* Asrc = Ag + (size_t)(m0 + rbase) * K3 + seg * 8;
    const __nv_bfloat16* Bsrc = Bg + (size_t)(n0 + rbase) * K3 + seg * 8;
    const size_t rstride = (size_t)32 * K3;

    const int wm = wid & 1;
    const int wn = wid >> 1;
    const int arow = wm * 64 + (lane & 15);
    const uint32_t akoff = (uint32_t)(lane >> 4) * 16u;
    const int brow = wn * 64 + ((lane >> 4) & 1) * 8 + (lane & 7);
    const uint32_t bkoff = (uint32_t)((lane >> 3) & 1) * 16u;

    float d[4][8][4];
#pragma unroll
    for (int i = 0; i < 4; i++)
#pragma unroll
        for (int j = 0; j < 8; j++)
#pragma unroll
            for (int q = 0; q < 4; q++) d[i][j][q] = 0.f;

#pragma unroll
    for (int c = 0; c < 3; c++) {
        uint32_t ab = sb0 + c * STG;
        uint32_t bb = ab + ASTG;
#pragma unroll
        for (int r = 0; r < 4; r++)
            cp16(ab + swA[r], Asrc + r * rstride + (size_t)c * 64);
#pragma unroll
        for (int r = 0; r < 8; r++)
            cp16(bb + swB[r], Bsrc + r * rstride + (size_t)c * 64);
        CP_COMMIT();
    }

    for (int c = 0; c < NC; ++c) {
        CP_WAIT2();
        __syncthreads();

        int slot = c & 3;
        uint32_t sA = sb0 + slot * STG;
        uint32_t sB = sA + ASTG;

#pragma unroll
        for (int ks = 0; ks < 4; ks++) {
            uint32_t kb = (uint32_t)ks * 32u;
            uint32_t a[4][4], bq[4][4];
#pragma unroll
            for (int i = 0; i < 4; i++) {
                uint32_t addr = sA + sw128((uint32_t)(arow + 16 * i) * 128u + kb + akoff);
                LDSM_X4(a[i][0], a[i][1], a[i][2], a[i][3], addr);
            }
#pragma unroll
            for (int j = 0; j < 4; j++) {
                uint32_t addr = sB + sw128((uint32_t)(brow + 16 * j) * 128u + kb + bkoff);
                LDSM_X4(bq[j][0], bq[j][1], bq[j][2], bq[j][3], addr);
            }
#pragma unroll
            for (int i = 0; i < 4; i++) {
#pragma unroll
                for (int j = 0; j < 4; j++) {
                    MMA16816(d[i][2 * j],     a[i], bq[j][0], bq[j][1]);
                    MMA16816(d[i][2 * j + 1], a[i], bq[j][2], bq[j][3]);
                }
            }
        }

        int cl = c + 3;
        if (cl < NC) {
            int ls = cl & 3;
            uint32_t ab = sb0 + ls * STG;
            uint32_t bb = ab + ASTG;
#pragma unroll
            for (int r = 0; r < 4; r++)
                cp16(ab + swA[r], Asrc + r * rstride + (size_t)cl * 64);
#pragma unroll
            for (int r = 0; r < 8; r++)
                cp16(bb + swB[r], Bsrc + r * rstride + (size_t)cl * 64);
            CP_COMMIT();
        }
    }

    const int erow = lane >> 2;
    const int ecol = (lane & 3) * 2;
#pragma unroll
    for (int i = 0; i < 4; i++) {
        int r0 = m0 + wm * 64 + i * 16 + erow;
#pragma unroll
        for (int j = 0; j < 8; j++) {
            int cbase = wn * 64 + j * 8 + ecol;
            float bz0 = sbias[cbase], bz1 = sbias[cbase + 1];
            float2 v0 = { d[i][j][0] + bz0, d[i][j][1] + bz1 };
            float2 v1 = { d[i][j][2] + bz0, d[i][j][3] + bz1 };
            *(float2*)(C + (size_t)r0 * Ncols + n0 + cbase)       = v0;
            *(float2*)(C + (size_t)(r0 + 8) * Ncols + n0 + cbase) = v1;
        }
    }
}

// ---------------- persistent LSTM scan v5 ----------------
// Dot layout identical to v3 (warp = k-chunk, lane = (gate, unit); broadcast
// smem reads). NEW: per-warp finalize (warp w owns unit w), 8 per-warp
// counters (128B apart), MLP poll by tid0.
__global__ __launch_bounds__(256, 1)
void lstm_seq(const float* __restrict__ Whh, const float* __restrict__ xg,
              const float* __restrict__ c0, float* __restrict__ hs_out,
              float* __restrict__ c_out, int T)
{
    __shared__ ulonglong2 sh2[256];   // h_t (1024 floats)
    __shared__ float sp[8][33];       // per-k-chunk partials

    const int tid  = threadIdx.x;
    const int warp = tid >> 5;
    const int lane = tid & 31;
    const int cta  = blockIdx.x;
    const int g    = lane >> 3;       // gate 0..3 (dot phase)
    const int jj   = lane & 7;        // local unit (dot phase)
    const int row  = g * HID + cta * 8 + jj;
    const int u    = cta * 8 + warp;  // unit finalized by this warp

    ulonglong2 w2[32];
    {
        const ulonglong2* wp =
            (const ulonglong2*)(Whh + (size_t)row * HID + warp * 128);
#pragma unroll
        for (int i = 0; i < 32; i++) w2[i] = wp[i];
    }

    float creg = c0[u];               // all lanes: broadcast load
    unsigned* ctrs = g_ctr8;

    // finalize-phase indexing: lane l -> k-chunk (l&7), gate (l>>3)
    const int fk = lane & 7;
    const int fg = lane >> 3;
    const bool is_head = (fk == 0);   // lanes 0,8,16,24

    for (int t = 0; t < T; ++t) {
        // stage h_t into smem (L1 bypass: written by other SMs)
        sh2[tid] = __ldcg(((const ulonglong2*)g_hbuf[t & 1]) + tid);
        float xgv = 0.f;
        if (is_head)
            xgv = __ldg(&xg[(size_t)t * G4 + (size_t)fg * HID + u]);
        __syncthreads();                              // (A) h staged

        // 128-wide dot, packed f32x2, warp-uniform smem reads (broadcast)
        ull a0 = 0, a1 = 0, a2 = 0, a3 = 0;
        const ulonglong2* hp = sh2 + warp * 32;
#pragma unroll
        for (int j = 0; j < 32; j += 2) {
            ulonglong2 ha = hp[j];
            ulonglong2 hb = hp[j + 1];
            FMA2(a0, w2[j].x, ha.x);
            FMA2(a1, w2[j].y, ha.y);
            FMA2(a2, w2[j + 1].x, hb.x);
            FMA2(a3, w2[j + 1].y, hb.y);
        }
        ull t01, t23, tt;
        ADD2(t01, a0, a1);
        ADD2(t23, a2, a3);
        ADD2(tt, t01, t23);
        uint32_t lo, hi;
        asm("mov.b64 {%0, %1}, %2;" : "=r"(lo), "=r"(hi) : "l"(tt));
        sp[warp][lane] = __uint_as_float(lo) + __uint_as_float(hi);
        __syncthreads();                              // (B) partials ready

        // per-warp finalize: warp w reduces unit u = cta*8+w.
        // lane l reads partial of (k-chunk fk, gate fg) for unit w:
        // sp[fk][fg*8 + w]; banks (fk + 8*fg + w) mod 32 -> conflict-free.
        float p = sp[fk][fg * 8 + warp];
        p += __shfl_down_sync(0xffffffffu, p, 4, 8);
        p += __shfl_down_sync(0xffffffffu, p, 2, 8);
        p += __shfl_down_sync(0xffffffffu, p, 1, 8);
        float s = p + xgv;                            // valid on head lanes

        float gi = __shfl_sync(0xffffffffu, s, 0);
        float gf = __shfl_sync(0xffffffffu, s, 8);
        float gz = __shfl_sync(0xffffffffu, s, 16);
        float go = __shfl_sync(0xffffffffu, s, 24);

        creg = sigf(gf) * creg + sigf(gi) * tanh_apx(gz);
        float hnew = sigf(go) * tanh_apx(creg);

        if (lane == 0) {
            g_hbuf[(t + 1) & 1][u] = hnew;
            if (hs_out) hs_out[(size_t)t * HID + u] = hnew;
            if (c_out && t == T - 1) c_out[u] = creg;
            // per-warp release to its own counter (128B apart)
            asm volatile("red.release.gpu.global.add.u32 [%0], 1;"
                         :: "l"(ctrs + warp * 32) : "memory");
        }

        // tid0 polls all 8 counters with independent loads (MLP)
        if (tid == 0) {
            unsigned tgt = (unsigned)(t + 1) * (unsigned)NCTA;
            for (;;) {
                unsigned v0, v1, v2, v3, v4, v5, v6, v7;
                asm volatile("ld.relaxed.gpu.global.u32 %0, [%1];" : "=r"(v0) : "l"(ctrs +   0));
                asm volatile("ld.relaxed.gpu.global.u32 %0, [%1];" : "=r"(v1) : "l"(ctrs +  32));
                asm volatile("ld.relaxed.gpu.global.u32 %0, [%1];" : "=r"(v2) : "l"(ctrs +  64));
                asm volatile("ld.relaxed.gpu.global.u32 %0, [%1];" : "=r"(v3) : "l"(ctrs +  96));
                asm volatile("ld.relaxed.gpu.global.u32 %0, [%1];" : "=r"(v4) : "l"(ctrs + 128));
                asm volatile("ld.relaxed.gpu.global.u32 %0, [%1];" : "=r"(v5) : "l"(ctrs + 160));
                asm volatile("ld.relaxed.gpu.global.u32 %0, [%1];" : "=r"(v6) : "l"(ctrs + 192));
                asm volatile("ld.relaxed.gpu.global.u32 %0, [%1];" : "=r"(v7) : "l"(ctrs + 224));
                if (v0 >= tgt && v1 >= tgt && v2 >= tgt && v3 >= tgt &&
                    v4 >= tgt && v5 >= tgt && v6 >= tgt && v7 >= tgt) break;
            }
            asm volatile("fence.acq_rel.gpu;" ::: "memory");
        }
        __syncthreads();                              // (C) barrier done
    }
}

// ---------------- launch ----------------
static void launch_gemm(const __nv_bfloat16* A, const __nv_bfloat16* B,
                        const float* b1, const float* b2, float* C,
                        int M, int N, int K3, int GN)
{
    int Mt = M / 128, Nt = N / 256;
    cudaFuncSetAttribute(gemm_mma3, cudaFuncAttributeMaxDynamicSharedMemorySize, GEMM_SMEM);
    gemm_mma3<<<Mt * Nt, 256, GEMM_SMEM>>>(A, B, b1, b2, C, Mt, K3, N, GN);
}

extern "C" void kernel_launch(void* const* d_in, const int* in_sizes, int n_in,
                              void* d_out, int out_size)
{
    const int*   e1       = (const int*)d_in[0];
    const int*   gt       = (const int*)d_in[1];
    const float* emb_i    = (const float*)d_in[2];
    const float* emb_o    = (const float*)d_in[3];
    const float* enc_Wih  = (const float*)d_in[4];
    const float* enc_Whh  = (const float*)d_in[5];
    const float* enc_bih  = (const float*)d_in[6];
    const float* enc_bhh  = (const float*)d_in[7];
    const float* dec_Wih  = (const float*)d_in[8];
    const float* dec_Whh  = (const float*)d_in[9];
    const float* dec_bih  = (const float*)d_in[10];
    const float* dec_bhh  = (const float*)d_in[11];
    const float* outW     = (const float*)d_in[12];
    const float* outb     = (const float*)d_in[13];
    float*       out      = (float*)d_out;

    float *xge, *xgd, *hs, *cenc, *czero;
    int* didx;
    __nv_bfloat16 *a3e, *a3d, *w3e, *w3d, *b3o, *a3h;
    cudaGetSymbolAddress((void**)&xge,   g_xg_enc);
    cudaGetSymbolAddress((void**)&xgd,   g_xg_dec);
    cudaGetSymbolAddress((void**)&hs,    g_hs);
    cudaGetSymbolAddress((void**)&cenc,  g_cenc);
    cudaGetSymbolAddress((void**)&czero, g_czero);
    cudaGetSymbolAddress((void**)&didx,  g_decidx);
    cudaGetSymbolAddress((void**)&a3e,   g_A3e);
    cudaGetSymbolAddress((void**)&a3d,   g_A3d);
    cudaGetSymbolAddress((void**)&w3e,   g_W3e);
    cudaGetSymbolAddress((void**)&w3d,   g_W3d);
    cudaGetSymbolAddress((void**)&b3o,   g_B3o);
    cudaGetSymbolAddress((void**)&a3h,   g_A3h);

    init0_kernel<<<8, 256>>>(gt);

    // bf16x3 conversions
    {
        long t1 = (long)G4 * EMB;
        conv_split<<<(int)(t1 / 4 / 256), 256>>>(enc_Wih, nullptr, w3e, EMB, t1, 1);
        conv_split<<<(int)(t1 / 4 / 256), 256>>>(dec_Wih, nullptr, w3d, EMB, t1, 1);
        long t2 = (long)OSIZE * HID;
        conv_split<<<(int)(t2 / 4 / 256), 256>>>(outW, nullptr, b3o, HID, t2, 1);
        long t3 = (long)TLEN * EMB;
        conv_split<<<(int)(t3 / 4 / 256), 256>>>(emb_i, e1,   a3e, EMB, t3, 0);
        conv_split<<<(int)(t3 / 4 / 256), 256>>>(emb_o, didx, a3d, EMB, t3, 0);
    }

    // x-gates
    launch_gemm(a3e, w3e, enc_bih, enc_bhh, xge, TLEN, G4, K3E, 16);
    launch_gemm(a3d, w3d, dec_bih, dec_bhh, xgd, TLEN, G4, K3E, 16);

    // encoder scan
    lstm_seq<<<NCTA, 256>>>(enc_Whh, xge, czero, nullptr, cenc, TLEN);
    init1_kernel<<<4, 256>>>();
    // decoder scan
    lstm_seq<<<NCTA, 256>>>(dec_Whh, xgd, cenc, hs, nullptr, TLEN);

    // logits
    {
        long t4 = (long)TLEN * HID;
        conv_split<<<(int)(t4 / 4 / 256), 256>>>(hs, nullptr, a3h, HID, t4, 0);
    }
    launch_gemm(a3h, b3o, outb, nullptr, out, TLEN, OSIZE, K3H, 25);
}

// round 10
// speedup vs baseline: 1.3257x; 1.3257x over previous
#include <cuda_runtime.h>
#include <cuda_bf16.h>
#include <math.h>
#include <stdint.h>

#define HID   1024
#define EMB   512
#define TLEN  2048
#define G4    4096
#define NCTA  128
#define OSIZE 32000
#define K3E   (3*EMB)
#define K3H   (3*HID)

typedef unsigned long long ull;

// ---------------- scratch ----------------
__device__ float g_xg_enc[(size_t)TLEN * G4];
__device__ float g_xg_dec[(size_t)TLEN * G4];
__device__ float g_hs[(size_t)TLEN * HID];
__device__ float g_hbuf[2][HID];
__device__ float g_cenc[HID];
__device__ float g_czero[HID];
__device__ int   g_decidx[TLEN];
__device__ unsigned g_ctr;
__device__ __nv_bfloat16 g_A3e[(size_t)TLEN * K3E];
__device__ __nv_bfloat16 g_A3d[(size_t)TLEN * K3E];
__device__ __nv_bfloat16 g_W3e[(size_t)G4 * K3E];
__device__ __nv_bfloat16 g_W3d[(size_t)G4 * K3E];
__device__ __nv_bfloat16 g_B3o[(size_t)OSIZE * K3H];
__device__ __nv_bfloat16 g_A3h[(size_t)TLEN * K3H];

// ---------------- helpers ----------------
__device__ __forceinline__ uint32_t s2u(const void* p) {
    return (uint32_t)__cvta_generic_to_shared(p);
}
__device__ __forceinline__ void cp16(uint32_t dst, const void* src) {
    asm volatile("cp.async.cg.shared.global [%0], [%1], 16;" :: "r"(dst), "l"(src) : "memory");
}
#define CP_COMMIT() asm volatile("cp.async.commit_group;" ::: "memory")
#define CP_WAIT2()  asm volatile("cp.async.wait_group 2;" ::: "memory")

#define LDSM_X4(r0, r1, r2, r3, addr) \
    asm volatile("ldmatrix.sync.aligned.m8n8.x4.shared.b16 {%0,%1,%2,%3}, [%4];" \
                 : "=r"(r0), "=r"(r1), "=r"(r2), "=r"(r3) : "r"(addr))

#define MMA16816(d, a, b0, b1) \
    asm volatile("mma.sync.aligned.m16n8k16.row.col.f32.bf16.bf16.f32 " \
                 "{%0,%1,%2,%3}, {%4,%5,%6,%7}, {%8,%9}, {%0,%1,%2,%3};" \
                 : "+f"((d)[0]), "+f"((d)[1]), "+f"((d)[2]), "+f"((d)[3]) \
                 : "r"((a)[0]), "r"((a)[1]), "r"((a)[2]), "r"((a)[3]), \
                   "r"(b0), "r"(b1))

#define FMA2(acc, w, h) \
    asm("fma.rn.f32x2 %0, %1, %2, %0;" : "+l"(acc) : "l"(w), "l"(h))
#define ADD2(d, a, b) \
    asm("add.rn.f32x2 %0, %1, %2;" : "=l"(d) : "l"(a), "l"(b))

__device__ __forceinline__ float tanh_apx(float x) {
    float r;
    asm("tanh.approx.f32 %0, %1;" : "=f"(r) : "f"(x));
    return r;
}
__device__ __forceinline__ float sigf(float x) {
    return fmaf(tanh_apx(0.5f * x), 0.5f, 0.5f);
}

static __device__ __forceinline__ uint32_t sw128(uint32_t off) {
    return off ^ ((off >> 3) & 0x70);
}

// ---------------- init kernels ----------------
__global__ void init0_kernel(const int* __restrict__ gt) {
    int i = blockIdx.x * blockDim.x + threadIdx.x;
    if (i == 0) g_ctr = 0u;
    if (i < HID) { g_hbuf[0][i] = 0.f; g_hbuf[1][i] = 0.f; g_czero[i] = 0.f; }
    if (i < TLEN) g_decidx[i] = (i == 0) ? 1 : gt[i - 1];
}
__global__ void init1_kernel() {
    int i = blockIdx.x * blockDim.x + threadIdx.x;
    if (i == 0) g_ctr = 0u;
    if (i < HID) g_hbuf[0][i] = g_cenc[i];
}

// ---------------- bf16 hi/lo split: mode 0 => [hi|lo|hi], mode 1 => [hi|hi|lo] ----------------
__global__ __launch_bounds__(256)
void conv_split(const float* __restrict__ src, const int* __restrict__ idx,
                __nv_bfloat16* __restrict__ dst, int K, long total, int mode)
{
    long i = ((long)blockIdx.x * blockDim.x + threadIdx.x) * 4;
    if (i >= total) return;
    int r = (int)(i / K);
    int k = (int)(i % K);
    int srow = idx ? idx[r] : r;
    float4 v = *(const float4*)(src + (size_t)srow * K + k);

    __nv_bfloat16 hx = __float2bfloat16_rn(v.x), hy = __float2bfloat16_rn(v.y);
    __nv_bfloat16 hz = __float2bfloat16_rn(v.z), hw = __float2bfloat16_rn(v.w);
    __nv_bfloat16 lx = __float2bfloat16_rn(v.x - __bfloat162float(hx));
    __nv_bfloat16 ly = __float2bfloat16_rn(v.y - __bfloat162float(hy));
    __nv_bfloat16 lz = __float2bfloat16_rn(v.z - __bfloat162float(hz));
    __nv_bfloat16 lw = __float2bfloat16_rn(v.w - __bfloat162float(hw));

    size_t base = (size_t)r * 3 * K;
    __nv_bfloat162 h01 = {hx, hy}, h23 = {hz, hw};
    __nv_bfloat162 l01 = {lx, ly}, l23 = {lz, lw};

    *(__nv_bfloat162*)(dst + base + k)     = h01;
    *(__nv_bfloat162*)(dst + base + k + 2) = h23;
    if (mode == 0) {
        *(__nv_bfloat162*)(dst + base + K + k)       = l01;
        *(__nv_bfloat162*)(dst + base + K + k + 2)   = l23;
        *(__nv_bfloat162*)(dst + base + 2*K + k)     = h01;
        *(__nv_bfloat162*)(dst + base + 2*K + k + 2) = h23;
    } else {
        *(__nv_bfloat162*)(dst + base + K + k)       = h01;
        *(__nv_bfloat162*)(dst + base + K + k + 2)   = h23;
        *(__nv_bfloat162*)(dst + base + 2*K + k)     = l01;
        *(__nv_bfloat162*)(dst + base + 2*K + k + 2) = l23;
    }
}

// ---------------- mma.sync bf16 GEMM (unchanged from R8) ----------------
#define ASTG 16384
#define BSTG 32768
#define STG  (ASTG + BSTG)
#define GEMM_SMEM (4 * STG + 2048)

__global__ __launch_bounds__(256, 1)
void gemm_mma3(const __nv_bfloat16* __restrict__ Ag, const __nv_bfloat16* __restrict__ Bg,
               const float* __restrict__ b1, const float* __restrict__ b2,
               float* __restrict__ C, int Mt, int K3, int Ncols, int GN)
{
    extern __shared__ char smem_raw[];
    const uint32_t sraw = s2u(smem_raw);
    const uint32_t sb0  = (sraw + 1023u) & ~1023u;
    float* sbias = (float*)(smem_raw + (sb0 - sraw) + 4 * STG);

    const int tid  = threadIdx.x;
    const int wid  = tid >> 5;
    const int lane = tid & 31;
    const int NC   = K3 >> 6;

    int gw  = Mt * GN;
    int gid = blockIdx.x / gw;
    int rem = blockIdx.x % gw;
    int m0 = (rem % Mt) * 128;
    int n0 = (gid * GN + rem / Mt) * 256;

    sbias[tid] = b1[n0 + tid] + (b2 ? b2[n0 + tid] : 0.f);

    const int rbase = tid >> 3;
    const int seg   = tid & 7;
    uint32_t swA[4], swB[8];
#pragma unroll
    for (int r = 0; r < 4; r++)
        swA[r] = sw128((uint32_t)(rbase + r * 32) * 128u + (uint32_t)seg * 16u);
#pragma unroll
    for (int r = 0; r < 8; r++)
        swB[r] = sw128((uint32_t)(rbase + r * 32) * 128u + (uint32_t)seg * 16u);
    const __nv_bfloat16* Asrc = Ag + (size_t)(m0 + rbase) * K3 + seg * 8;
    const __nv_bfloat16* Bsrc = Bg + (size_t)(n0 + rbase) * K3 + seg * 8;
    const size_t rstride = (size_t)32 * K3;

    const int wm = wid & 1;
    const int wn = wid >> 1;
    const int arow = wm * 64 + (lane & 15);
    const uint32_t akoff = (uint32_t)(lane >> 4) * 16u;
    const int brow = wn * 64 + ((lane >> 4) & 1) * 8 + (lane & 7);
    const uint32_t bkoff = (uint32_t)((lane >> 3) & 1) * 16u;

    float d[4][8][4];
#pragma unroll
    for (int i = 0; i < 4; i++)
#pragma unroll
        for (int j = 0; j < 8; j++)
#pragma unroll
            for (int q = 0; q < 4; q++) d[i][j][q] = 0.f;

#pragma unroll
    for (int c = 0; c < 3; c++) {
        uint32_t ab = sb0 + c * STG;
        uint32_t bb = ab + ASTG;
#pragma unroll
        for (int r = 0; r < 4; r++)
            cp16(ab + swA[r], Asrc + r * rstride + (size_t)c * 64);
#pragma unroll
        for (int r = 0; r < 8; r++)
            cp16(bb + swB[r], Bsrc + r * rstride + (size_t)c * 64);
        CP_COMMIT();
    }

    for (int c = 0; c < NC; ++c) {
        CP_WAIT2();
        __syncthreads();

        int slot = c & 3;
        uint32_t sA = sb0 + slot * STG;
        uint32_t sB = sA + ASTG;

#pragma unroll
        for (int ks = 0; ks < 4; ks++) {
            uint32_t kb = (uint32_t)ks * 32u;
            uint32_t a[4][4], bq[4][4];
#pragma unroll
            for (int i = 0; i < 4; i++) {
                uint32_t addr = sA + sw128((uint32_t)(arow + 16 * i) * 128u + kb + akoff);
                LDSM_X4(a[i][0], a[i][1], a[i][2], a[i][3], addr);
            }
#pragma unroll
            for (int j = 0; j < 4; j++) {
                uint32_t addr = sB + sw128((uint32_t)(brow + 16 * j) * 128u + kb + bkoff);
                LDSM_X4(bq[j][0], bq[j][1], bq[j][2], bq[j][3], addr);
            }
#pragma unroll
            for (int i = 0; i < 4; i++) {
#pragma unroll
                for (int j = 0; j < 4; j++) {
                    MMA16816(d[i][2 * j],     a[i], bq[j][0], bq[j][1]);
                    MMA16816(d[i][2 * j + 1], a[i], bq[j][2], bq[j][3]);
                }
            }
        }

        int cl = c + 3;
        if (cl < NC) {
            int ls = cl & 3;
            uint32_t ab = sb0 + ls * STG;
            uint32_t bb = ab + ASTG;
#pragma unroll
            for (int r = 0; r < 4; r++)
                cp16(ab + swA[r], Asrc + r * rstride + (size_t)cl * 64);
#pragma unroll
            for (int r = 0; r < 8; r++)
                cp16(bb + swB[r], Bsrc + r * rstride + (size_t)cl * 64);
            CP_COMMIT();
        }
    }

    const int erow = lane >> 2;
    const int ecol = (lane & 3) * 2;
#pragma unroll
    for (int i = 0; i < 4; i++) {
        int r0 = m0 + wm * 64 + i * 16 + erow;
#pragma unroll
        for (int j = 0; j < 8; j++) {
            int cbase = wn * 64 + j * 8 + ecol;
            float bz0 = sbias[cbase], bz1 = sbias[cbase + 1];
            float2 v0 = { d[i][j][0] + bz0, d[i][j][1] + bz1 };
            float2 v1 = { d[i][j][2] + bz0, d[i][j][3] + bz1 };
            *(float2*)(C + (size_t)r0 * Ncols + n0 + cbase)       = v0;
            *(float2*)(C + (size_t)(r0 + 8) * Ncols + n0 + cbase) = v1;
        }
    }
}

// ---------------- persistent LSTM scan v6 ----------------
// Exact R8 (v3) structure — the 1.6us/step champion — with ONE change:
// xg is register double-buffered one step ahead so its DRAM latency
// (~600cyc > the ~450cyc overlap window it had) is fully hidden.
__global__ __launch_bounds__(256, 1)
void lstm_seq(const float* __restrict__ Whh, const float* __restrict__ xg,
              const float* __restrict__ c0, float* __restrict__ hs_out,
              float* __restrict__ c_out, int T)
{
    __shared__ ulonglong2 sh2[256];   // h_t (1024 floats)
    __shared__ float sp[8][33];       // per-warp partials

    const int tid  = threadIdx.x;
    const int warp = tid >> 5;
    const int lane = tid & 31;
    const int cta  = blockIdx.x;
    const int g    = lane >> 3;       // gate 0..3
    const int jj   = lane & 7;        // local hidden unit
    const int row  = g * HID + cta * 8 + jj;

    ulonglong2 w2[32];
    {
        const ulonglong2* wp =
            (const ulonglong2*)(Whh + (size_t)row * HID + warp * 128);
#pragma unroll
        for (int i = 0; i < 32; i++) w2[i] = wp[i];
    }

    float creg = 0.f;
    if (tid < 8) creg = c0[cta * 8 + tid];
    unsigned* ctr = &g_ctr;

    // prefetch xg for step 0 (tid<32 only; one float per thread)
    const float* xgp = xg + (size_t)g * HID + cta * 8 + jj;   // + t*G4
    float xgv_next = 0.f;
    if (tid < 32) xgv_next = __ldg(xgp);

    for (int t = 0; t < T; ++t) {
        // stage h_t into smem (L1 bypass: written by other SMs)
        sh2[tid] = __ldcg(((const ulonglong2*)g_hbuf[t & 1]) + tid);
        float xgv = xgv_next;
        // prefetch next step's xg (full step of latency cover)
        if (tid < 32 && t + 1 < T)
            xgv_next = __ldg(xgp + (size_t)(t + 1) * G4);
        __syncthreads();                              // (A) h staged

        // 128-wide dot, packed f32x2, warp-uniform smem reads (broadcast)
        ull a0 = 0, a1 = 0, a2 = 0, a3 = 0;
        const ulonglong2* hp = sh2 + warp * 32;
#pragma unroll
        for (int j = 0; j < 32; j += 2) {
            ulonglong2 ha = hp[j];
            ulonglong2 hb = hp[j + 1];
            FMA2(a0, w2[j].x, ha.x);
            FMA2(a1, w2[j].y, ha.y);
            FMA2(a2, w2[j + 1].x, hb.x);
            FMA2(a3, w2[j + 1].y, hb.y);
        }
        ull t01, t23, tt;
        ADD2(t01, a0, a1);
        ADD2(t23, a2, a3);
        ADD2(tt, t01, t23);
        uint32_t lo, hi;
        asm("mov.b64 {%0, %1}, %2;" : "=r"(lo), "=r"(hi) : "l"(tt));
        sp[warp][lane] = __uint_as_float(lo) + __uint_as_float(hi);
        __syncthreads();                              // (B) partials ready

        if (warp == 0) {
            float s = xgv;
#pragma unroll
            for (int w = 0; w < 8; w++) s += sp[w][lane];
            float gi = __shfl_sync(0xffffffffu, s, lane & 7);
            float gf = __shfl_sync(0xffffffffu, s, 8 + (lane & 7));
            float gz = __shfl_sync(0xffffffffu, s, 16 + (lane & 7));
            float go = __shfl_sync(0xffffffffu, s, 24 + (lane & 7));
            if (lane < 8) {
                creg = sigf(gf) * creg + sigf(gi) * tanh_apx(gz);
                float hnew = sigf(go) * tanh_apx(creg);
                int hidx = cta * 8 + lane;
                g_hbuf[(t + 1) & 1][hidx] = hnew;
                if (hs_out) hs_out[(size_t)t * HID + hidx] = hnew;
                if (c_out && t == T - 1) c_out[hidx] = creg;
            }
            __syncwarp();
            if (lane == 0) {
                asm volatile("red.release.gpu.global.add.u32 [%0], 1;"
                             :: "l"(ctr) : "memory");
                unsigned tgt = (unsigned)(t + 1) * (unsigned)NCTA;
                unsigned v;
                do {
                    asm volatile("ld.acquire.gpu.global.u32 %0, [%1];"
                                 : "=r"(v) : "l"(ctr) : "memory");
                } while (v < tgt);
            }
        }
        __syncthreads();                              // (C) barrier done
    }
}

// ---------------- launch ----------------
static void launch_gemm(const __nv_bfloat16* A, const __nv_bfloat16* B,
                        const float* b1, const float* b2, float* C,
                        int M, int N, int K3, int GN)
{
    int Mt = M / 128, Nt = N / 256;
    cudaFuncSetAttribute(gemm_mma3, cudaFuncAttributeMaxDynamicSharedMemorySize, GEMM_SMEM);
    gemm_mma3<<<Mt * Nt, 256, GEMM_SMEM>>>(A, B, b1, b2, C, Mt, K3, N, GN);
}

extern "C" void kernel_launch(void* const* d_in, const int* in_sizes, int n_in,
                              void* d_out, int out_size)
{
    const int*   e1       = (const int*)d_in[0];
    const int*   gt       = (const int*)d_in[1];
    const float* emb_i    = (const float*)d_in[2];
    const float* emb_o    = (const float*)d_in[3];
    const float* enc_Wih  = (const float*)d_in[4];
    const float* enc_Whh  = (const float*)d_in[5];
    const float* enc_bih  = (const float*)d_in[6];
    const float* enc_bhh  = (const float*)d_in[7];
    const float* dec_Wih  = (const float*)d_in[8];
    const float* dec_Whh  = (const float*)d_in[9];
    const float* dec_bih  = (const float*)d_in[10];
    const float* dec_bhh  = (const float*)d_in[11];
    const float* outW     = (const float*)d_in[12];
    const float* outb     = (const float*)d_in[13];
    float*       out      = (float*)d_out;

    float *xge, *xgd, *hs, *cenc, *czero;
    int* didx;
    __nv_bfloat16 *a3e, *a3d, *w3e, *w3d, *b3o, *a3h;
    cudaGetSymbolAddress((void**)&xge,   g_xg_enc);
    cudaGetSymbolAddress((void**)&xgd,   g_xg_dec);
    cudaGetSymbolAddress((void**)&hs,    g_hs);
    cudaGetSymbolAddress((void**)&cenc,  g_cenc);
    cudaGetSymbolAddress((void**)&czero, g_czero);
    cudaGetSymbolAddress((void**)&didx,  g_decidx);
    cudaGetSymbolAddress((void**)&a3e,   g_A3e);
    cudaGetSymbolAddress((void**)&a3d,   g_A3d);
    cudaGetSymbolAddress((void**)&w3e,   g_W3e);
    cudaGetSymbolAddress((void**)&w3d,   g_W3d);
    cudaGetSymbolAddress((void**)&b3o,   g_B3o);
    cudaGetSymbolAddress((void**)&a3h,   g_A3h);

    init0_kernel<<<8, 256>>>(gt);

    // bf16x3 conversions
    {
        long t1 = (long)G4 * EMB;
        conv_split<<<(int)(t1 / 4 / 256), 256>>>(enc_Wih, nullptr, w3e, EMB, t1, 1);
        conv_split<<<(int)(t1 / 4 / 256), 256>>>(dec_Wih, nullptr, w3d, EMB, t1, 1);
        long t2 = (long)OSIZE * HID;
        conv_split<<<(int)(t2 / 4 / 256), 256>>>(outW, nullptr, b3o, HID, t2, 1);
        long t3 = (long)TLEN * EMB;
        conv_split<<<(int)(t3 / 4 / 256), 256>>>(emb_i, e1,   a3e, EMB, t3, 0);
        conv_split<<<(int)(t3 / 4 / 256), 256>>>(emb_o, didx, a3d, EMB, t3, 0);
    }

    // x-gates
    launch_gemm(a3e, w3e, enc_bih, enc_bhh, xge, TLEN, G4, K3E, 16);
    launch_gemm(a3d, w3d, dec_bih, dec_bhh, xgd, TLEN, G4, K3E, 16);

    // encoder scan
    lstm_seq<<<NCTA, 256>>>(enc_Whh, xge, czero, nullptr, cenc, TLEN);
    init1_kernel<<<4, 256>>>();
    // decoder scan
    lstm_seq<<<NCTA, 256>>>(dec_Whh, xgd, cenc, hs, nullptr, TLEN);

    // logits
    {
        long t4 = (long)TLEN * HID;
        conv_split<<<(int)(t4 / 4 / 256), 256>>>(hs, nullptr, a3h, HID, t4, 0);
    }
    launch_gemm(a3h, b3o, outb, nullptr, out, TLEN, OSIZE, K3H, 25);
}